// round 12
// baseline (speedup 1.0000x reference)
#include <cuda_runtime.h>
#include <cstdint>
#include <cstddef>

#define NPTS 80000
#define H    32
#define KPTS 15
#define CIN  128
#define COUT 256
#define D2   64
#define INFL 0.4f
#define EPS  1e-5f
#define SLOPE 0.2f

// ---------------- device scratch ----------------
__device__ __align__(128) float g_x1 [(size_t)NPTS * D2];           // unary_1 out
__device__ __align__(128) float g_fk [(size_t)NPTS * KPTS * D2];    // [n][k*64+d]
__device__ __align__(128) float g_xkp[(size_t)NPTS * D2];           // KPConv out
__device__ __align__(128) float g_y2 [(size_t)NPTS * COUT];         // unary_2 pre-BN
__device__ __align__(128) float g_part[256 * 2 * COUT];
__device__ __align__(128) float g_bn1 [2 * D2];
__device__ __align__(128) float g_bn2 [2 * COUT];
__device__ __align__(128) float g_bnsc[2 * COUT];

__device__ __forceinline__ float leaky(float v) { return v > 0.f ? v : v * SLOPE; }

// ---------------- double-buffered fp32 GEMM (unchanged from R9) ----------------
template<int KD, int ND>
__global__ __launch_bounds__(128, 6)
void gemm_k(const float* __restrict__ A, const float* __restrict__ B,
            float* __restrict__ C) {
    __shared__ __align__(16) float sA[2][32][68];   // [buf][k][r] transposed
    __shared__ __align__(16) float sB[2][32][68];   // [buf][k][c]

    const int tid  = threadIdx.x;
    const int rr   = (tid >> 4) * 8;
    const int cc   = (tid & 15) * 4;
    const int row0 = blockIdx.x * 64;
    const int col0 = blockIdx.y * 64;

    float acc[8][4];
#pragma unroll
    for (int i = 0; i < 8; i++)
#pragma unroll
        for (int j = 0; j < 4; j++) acc[i][j] = 0.f;

    float4 va[4], vb[4];
    constexpr int NT = KD / 32;

#pragma unroll
    for (int i = 0; i < 4; i++) {
        const int id = tid + i * 128;
        va[i] = *(const float4*)&A[(size_t)(row0 + (id >> 3)) * KD + (id & 7) * 4];
        vb[i] = *(const float4*)&B[(size_t)(id >> 4) * ND + col0 + (id & 15) * 4];
    }
#pragma unroll
    for (int i = 0; i < 4; i++) {
        const int id = tid + i * 128;
        const int r = id >> 3, c4 = (id & 7) * 4;
        sA[0][c4 + 0][r] = va[i].x;
        sA[0][c4 + 1][r] = va[i].y;
        sA[0][c4 + 2][r] = va[i].z;
        sA[0][c4 + 3][r] = va[i].w;
        *(float4*)&sB[0][id >> 4][(id & 15) * 4] = vb[i];
    }
    __syncthreads();

    for (int t = 0; t < NT; t++) {
        const int cur = t & 1;
        if (t + 1 < NT) {
            const int k0 = (t + 1) * 32;
#pragma unroll
            for (int i = 0; i < 4; i++) {
                const int id = tid + i * 128;
                va[i] = *(const float4*)&A[(size_t)(row0 + (id >> 3)) * KD + k0 + (id & 7) * 4];
                vb[i] = *(const float4*)&B[(size_t)(k0 + (id >> 4)) * ND + col0 + (id & 15) * 4];
            }
        }
#pragma unroll
        for (int kk = 0; kk < 32; kk++) {
            const float4 b  = *(const float4*)&sB[cur][kk][cc];
            const float4 a0 = *(const float4*)&sA[cur][kk][rr];
            const float4 a1 = *(const float4*)&sA[cur][kk][rr + 4];
            acc[0][0] += a0.x * b.x; acc[0][1] += a0.x * b.y; acc[0][2] += a0.x * b.z; acc[0][3] += a0.x * b.w;
            acc[1][0] += a0.y * b.x; acc[1][1] += a0.y * b.y; acc[1][2] += a0.y * b.z; acc[1][3] += a0.y * b.w;
            acc[2][0] += a0.z * b.x; acc[2][1] += a0.z * b.y; acc[2][2] += a0.z * b.z; acc[2][3] += a0.z * b.w;
            acc[3][0] += a0.w * b.x; acc[3][1] += a0.w * b.y; acc[3][2] += a0.w * b.z; acc[3][3] += a0.w * b.w;
            acc[4][0] += a1.x * b.x; acc[4][1] += a1.x * b.y; acc[4][2] += a1.x * b.z; acc[4][3] += a1.x * b.w;
            acc[5][0] += a1.y * b.x; acc[5][1] += a1.y * b.y; acc[5][2] += a1.y * b.z; acc[5][3] += a1.y * b.w;
            acc[6][0] += a1.z * b.x; acc[6][1] += a1.z * b.y; acc[6][2] += a1.z * b.z; acc[6][3] += a1.z * b.w;
            acc[7][0] += a1.w * b.x; acc[7][1] += a1.w * b.y; acc[7][2] += a1.w * b.z; acc[7][3] += a1.w * b.w;
        }
        if (t + 1 < NT) {
            const int nxt = cur ^ 1;
#pragma unroll
            for (int i = 0; i < 4; i++) {
                const int id = tid + i * 128;
                const int r = id >> 3, c4 = (id & 7) * 4;
                sA[nxt][c4 + 0][r] = va[i].x;
                sA[nxt][c4 + 1][r] = va[i].y;
                sA[nxt][c4 + 2][r] = va[i].z;
                sA[nxt][c4 + 3][r] = va[i].w;
                *(float4*)&sB[nxt][id >> 4][(id & 15) * 4] = vb[i];
            }
            __syncthreads();
        }
    }

#pragma unroll
    for (int i = 0; i < 8; i++) {
        *(float4*)&C[(size_t)(row0 + rr + i) * ND + col0 + cc] =
            make_float4(acc[i][0], acc[i][1], acc[i][2], acc[i][3]);
    }
}

// ---------------- column stats (deterministic 2-stage) ----------------
template<int C>
__global__ __launch_bounds__(256)
void colstats(const float* __restrict__ y, float* __restrict__ part) {
    const int tid = threadIdx.x, bid = blockIdx.x;
    if (C == 256) {
        float s = 0.f, q = 0.f;
        for (int r = bid; r < NPTS; r += 256) {
            float v = y[(size_t)r * 256 + tid];
            s += v; q += v * v;
        }
        part[bid * 512 + tid] = s;
        part[bid * 512 + 256 + tid] = q;
    } else {
        const int c = tid & 63, rg = tid >> 6;
        float s = 0.f, q = 0.f;
        for (int r = bid * 4 + rg; r < NPTS; r += 1024) {
            float v = y[(size_t)r * 64 + c];
            s += v; q += v * v;
        }
        __shared__ float sh[2][256];
        sh[0][tid] = s; sh[1][tid] = q;
        __syncthreads();
        if (tid < 64) {
            s = sh[0][tid] + sh[0][tid + 64] + sh[0][tid + 128] + sh[0][tid + 192];
            q = sh[1][tid] + sh[1][tid + 64] + sh[1][tid + 128] + sh[1][tid + 192];
            part[bid * 128 + tid] = s;
            part[bid * 128 + 64 + tid] = q;
        }
    }
}

template<int C>
__global__ void finalize_bn(const float* __restrict__ part,
                            const float* __restrict__ g, const float* __restrict__ b,
                            float* __restrict__ bnout) {
    const int c = threadIdx.x;
    float s = 0.f, q = 0.f;
    for (int i = 0; i < 256; i++) {
        s += part[i * 2 * C + c];
        q += part[i * 2 * C + C + c];
    }
    const float mean = s / (float)NPTS;
    const float var = q / (float)NPTS - mean * mean;
    const float sc = g[c] * rsqrtf(var + EPS);
    bnout[c] = sc;
    bnout[C + c] = b[c] - mean * sc;
}

// ---------------- BN1 apply + leaky relu (in place) ----------------
__global__ __launch_bounds__(256)
void bn_act_64(float* __restrict__ x, const float* __restrict__ bn) {
    const size_t i = (size_t)blockIdx.x * 256 + threadIdx.x;
    float4 v = ((float4*)x)[i];
    const int c = (int)((i * 4) & 63);
    v.x = leaky(v.x * bn[c + 0] + bn[64 + c + 0]);
    v.y = leaky(v.y * bn[c + 1] + bn[64 + c + 1]);
    v.z = leaky(v.z * bn[c + 2] + bn[64 + c + 2]);
    v.w = leaky(v.w * bn[c + 3] + bn[64 + c + 3]);
    ((float4*)x)[i] = v;
}

// ---------------- KPConv, SPARSE: warp-per-point, ballot masks ----------------
// 4 points/block, 128 threads. Phase A: lane=h computes 15 influence weights,
// per-k nonzero bitmask over h via warp ballot. Phase A2: stage the 32 gathered
// x1 rows (64 floats each) in smem. Phase B: per k (unrolled, register acc),
// iterate only active h via ffs — skipped terms are exact 0.0f, so the result
// is bitwise identical to the dense loop (h ascending order preserved).
#define PPB 4
__global__ __launch_bounds__(128)
void kpconv_kernel(const float* __restrict__ xyz, const int* __restrict__ nbr,
                   const float* __restrict__ kp) {
    __shared__ __align__(16) float s_v[PPB][H][D2];     // 32 KB
    __shared__ float    s_w[PPB][H][16];                // 8 KB
    __shared__ int      s_nbr[PPB][H];
    __shared__ unsigned s_mask[PPB][KPTS];
    __shared__ float    s_kp[KPTS * 3];

    const int tid  = threadIdx.x;
    const int wp   = tid >> 5;         // point slot 0..3
    const int lane = tid & 31;
    const int n    = blockIdx.x * PPB + wp;

    if (tid < KPTS * 3) s_kp[tid] = kp[tid];
    __syncthreads();

    // ---- phase A: weights + masks (lane = h) ----
    {
        const int h = lane;
        const int j = nbr[n * H + h];
        s_nbr[wp][h] = j;
        const float dx = xyz[j * 3 + 0] - xyz[n * 3 + 0];
        const float dy = xyz[j * 3 + 1] - xyz[n * 3 + 1];
        const float dz = xyz[j * 3 + 2] - xyz[n * 3 + 2];
        float w[KPTS];
#pragma unroll
        for (int k = 0; k < KPTS; k++) {
            const float ex = dx - s_kp[k * 3 + 0];
            const float ey = dy - s_kp[k * 3 + 1];
            const float ez = dz - s_kp[k * 3 + 2];
            const float sq = ex * ex + ey * ey + ez * ez;
            w[k] = fmaxf(1.f - sqrtf(sq) * (1.f / INFL), 0.f);
            s_w[wp][h][k] = w[k];
        }
#pragma unroll
        for (int k = 0; k < KPTS; k++) {
            const unsigned m = __ballot_sync(0xffffffffu, w[k] > 0.f);
            if (lane == 0) s_mask[wp][k] = m;
        }
    }
    __syncwarp();

    // ---- phase A2: stage x1 rows ----
    for (int h = 0; h < H; h++) {
        const int j = s_nbr[wp][h];
        *(float2*)&s_v[wp][h][lane * 2] =
            *(const float2*)&g_x1[(size_t)j * D2 + lane * 2];
    }
    __syncwarp();

    // ---- phase B: sparse accumulate, thread owns 2 d's ----
    float acc[KPTS][2];
#pragma unroll
    for (int k = 0; k < KPTS; k++) { acc[k][0] = 0.f; acc[k][1] = 0.f; }

#pragma unroll
    for (int k = 0; k < KPTS; k++) {
        unsigned m = s_mask[wp][k];
        while (m) {
            const int h = __ffs(m) - 1;
            m &= m - 1;
            const float w = s_w[wp][h][k];
            const float2 v = *(const float2*)&s_v[wp][h][lane * 2];
            acc[k][0] += w * v.x;
            acc[k][1] += w * v.y;
        }
    }

    float* dst = &g_fk[(size_t)n * (KPTS * D2) + lane * 2];
#pragma unroll
    for (int k = 0; k < KPTS; k++) {
        *(float2*)&dst[k * D2] = make_float2(acc[k][0], acc[k][1]);
    }
}

// ---------------- final combine ----------------
__global__ __launch_bounds__(256)
void combine_kernel(const float* __restrict__ y2, float* __restrict__ out,
                    const float* __restrict__ bn2, const float* __restrict__ bnsc) {
    const size_t i = (size_t)blockIdx.x * 256 + threadIdx.x;
    const int c = (int)((i * 4) & 255);
    float4 a = ((const float4*)y2)[i];
    float4 s = ((float4*)out)[i];
    float4 r;
    r.x = leaky(a.x * bn2[c + 0] + bn2[256 + c + 0]) + (s.x * bnsc[c + 0] + bnsc[256 + c + 0]);
    r.y = leaky(a.y * bn2[c + 1] + bn2[256 + c + 1]) + (s.y * bnsc[c + 1] + bnsc[256 + c + 1]);
    r.z = leaky(a.z * bn2[c + 2] + bn2[256 + c + 2]) + (s.z * bnsc[c + 2] + bnsc[256 + c + 2]);
    r.w = leaky(a.w * bn2[c + 3] + bn2[256 + c + 3]) + (s.w * bnsc[c + 3] + bnsc[256 + c + 3]);
    ((float4*)out)[i] = r;
}

// ---------------- launcher ----------------
extern "C" void kernel_launch(void* const* d_in, const int* in_sizes, int n_in,
                              void* d_out, int out_size) {
    const float* feats = (const float*)d_in[0];
    const float* xyz   = (const float*)d_in[1];
    const int*   nbr   = (const int*)d_in[3];
    const float* W1    = (const float*)d_in[4];
    const float* g1    = (const float*)d_in[5];
    const float* b1    = (const float*)d_in[6];
    const float* kpp   = (const float*)d_in[7];
    const float* kpw   = (const float*)d_in[8];   // [15*64][64] natural layout
    const float* W2    = (const float*)d_in[9];
    const float* g2    = (const float*)d_in[10];
    const float* b2    = (const float*)d_in[11];
    const float* Wsc   = (const float*)d_in[12];
    const float* gsc   = (const float*)d_in[13];
    const float* bsc   = (const float*)d_in[14];
    float* out = (float*)d_out;

    void *px1, *pfk, *pxkp, *py2, *ppart, *pbn1, *pbn2, *pbnsc;
    cudaGetSymbolAddress(&px1, g_x1);
    cudaGetSymbolAddress(&pfk, g_fk);
    cudaGetSymbolAddress(&pxkp, g_xkp);
    cudaGetSymbolAddress(&py2, g_y2);
    cudaGetSymbolAddress(&ppart, g_part);
    cudaGetSymbolAddress(&pbn1, g_bn1);
    cudaGetSymbolAddress(&pbn2, g_bn2);
    cudaGetSymbolAddress(&pbnsc, g_bnsc);
    float *x1 = (float*)px1, *fk = (float*)pfk, *xkp = (float*)pxkp;
    float *y2 = (float*)py2, *part = (float*)ppart;
    float *bn1 = (float*)pbn1, *bn2 = (float*)pbn2, *bnsc = (float*)pbnsc;

    // 1) unary_1: x1 = feats @ W1  [N,64]
    gemm_k<128, 64><<<dim3(1250, 1), 128>>>(feats, W1, x1);
    // 2) BN1 + act
    colstats<64><<<256, 256>>>(x1, part);
    finalize_bn<64><<<1, 64>>>(part, g1, b1, bn1);
    bn_act_64<<<NPTS * 64 / 4 / 256, 256>>>(x1, bn1);
    // 3) KPConv (sparse) -> fk [N, 960]
    kpconv_kernel<<<NPTS / PPB, 128>>>(xyz, nbr, kpp);
    // 4) x_kp = fk @ kp_weights  [N,960]@[960,64]
    gemm_k<960, 64><<<dim3(1250, 1), 128>>>(fk, kpw, xkp);
    // 5) y2 = x_kp @ W2  [N,256]
    gemm_k<64, 256><<<dim3(1250, 4), 128>>>(xkp, W2, y2);
    colstats<256><<<256, 256>>>(y2, part);
    finalize_bn<256><<<1, 256>>>(part, g2, b2, bn2);
    // 6) shortcut -> out raw
    gemm_k<128, 256><<<dim3(1250, 4), 128>>>(feats, Wsc, out);
    colstats<256><<<256, 256>>>(out, part);
    finalize_bn<256><<<1, 256>>>(part, gsc, bsc, bnsc);
    // 7) combine
    combine_kernel<<<NPTS * 256 / 4 / 256, 256>>>(y2, out, bn2, bnsc);
}